// round 10
// baseline (speedup 1.0000x reference)
#include <cuda_runtime.h>
#include <cstdint>

#define NN 100000
#define NE 1000000
#define D  64
#define MP 3

#define TILE 2048
#define NT ((NN + TILE - 1) / TILE)

// Scratch (__device__ globals per allocation-free rule)
__device__ float mg_h[(size_t)MP * NN * D];       // transformed features
__device__ float mg_deg[MP * NN];                 // dinv
__device__ unsigned long long mg_pack[MP * NN];   // count<<44 | fixp deg sum
__device__ int   mg_count[MP * NN];               // edges per dest node
__device__ int   mg_off[MP * NN];                 // CSR start offsets
__device__ int   mg_ctr[MP * NN];                 // running fill cursors
__device__ int2  mg_edge[(size_t)MP * NE];        // packed (src row, norm)
__device__ int   mg_tiletot[MP * NT];
__device__ uint32_t mg_wtf[MP * D * D];           // tf32-converted W
__device__ int   mg_sh;                           // 0 = int32 idx, 1 = int64

// ---------------------------------------------------------------------------
// Fused: zero pack; block 0 warp 0 sniffs edge dtype.
// ---------------------------------------------------------------------------
__global__ void mz_init(const int* __restrict__ ei32) {
    int i = blockIdx.x * blockDim.x + threadIdx.x;
    if (i < MP * NN) mg_pack[i] = 0ull;
    if (blockIdx.x == 0 && threadIdx.x < 32) {
        int t = threadIdx.x;
        int nz = 0;
        for (int k = 0; k < 8; k++) {
            int s = (t * 8 + k) * 1009;
            nz |= (ei32[2 * s + 1] != 0);
        }
        unsigned b = __ballot_sync(0xffffffffu, nz);
        if (t == 0) mg_sh = (b == 0u) ? 1 : 0;
    }
}

__device__ __forceinline__ int ld_idx(const int* p, size_t pos, int sh) {
    return p[pos << sh];
}

// W -> tf32 scratch (one-shot, 12288 elems)
__device__ __forceinline__ uint32_t f2tf32(float f) {
    uint32_t u;
    asm("cvt.rna.tf32.f32 %0, %1;" : "=r"(u) : "f"(f));
    return u;
}
__global__ void mz_wcvt(const float* __restrict__ W) {
    int i = blockIdx.x * blockDim.x + threadIdx.x;
    if (i < MP * D * D) mg_wtf[i] = f2tf32(W[i]);
}

// ---------------------------------------------------------------------------
// Single packed u64 atomic per edge: count++ AND deg += ew (2^-24 fixpoint)
// ---------------------------------------------------------------------------
__global__ void mz_hist(const int* __restrict__ ei32,
                        const float* __restrict__ ew) {
    int mp = blockIdx.y;
    int sh = mg_sh;
    size_t colbase = (size_t)mp * 2 * NE + NE;
    const float* ewp = ew + (size_t)mp * NE;
    unsigned long long* pk = mg_pack + (size_t)mp * NN;
    int stride = gridDim.x * blockDim.x;
    for (int e = blockIdx.x * blockDim.x + threadIdx.x; e < NE; e += stride) {
        int c = ld_idx(ei32, colbase + e, sh);
        unsigned long long frac =
            (unsigned long long)__float2uint_rn(ewp[e] * 16777216.0f);
        atomicAdd(pk + c, (1ull << 44) | frac);
    }
}

// ---------------------------------------------------------------------------
// Phase A of decoupled scan, fused with pack -> (count, dinv).
// ---------------------------------------------------------------------------
__global__ __launch_bounds__(256) void mz_scanA() {
    __shared__ int wtot[8];
    __shared__ int wpre[8];
    int mp = blockIdx.y;
    int tile = blockIdx.x;
    int t = threadIdx.x;
    int lane = t & 31;
    int warp = t >> 5;
    const unsigned long long* pk = mg_pack + (size_t)mp * NN;
    int* cnt = mg_count + (size_t)mp * NN;
    int* off = mg_off + (size_t)mp * NN;
    float* deg = mg_deg + (size_t)mp * NN;

    int base = tile * TILE + t * 8;
    int v[8];
#pragma unroll
    for (int k = 0; k < 8; k++) {
        int i = base + k;
        if (i < NN) {
            unsigned long long p = pk[i];
            int c = (int)(p >> 44);
            float d = (float)(p & ((1ull << 44) - 1)) * (1.0f / 16777216.0f);
            v[k] = c;
            cnt[i] = c;
            deg[i] = (d > 0.f) ? rsqrtf(d) : 0.f;
        } else {
            v[k] = 0;
        }
    }
    int mysum = 0;
#pragma unroll
    for (int k = 0; k < 8; k++) mysum += v[k];

    int inc = mysum;
#pragma unroll
    for (int o = 1; o < 32; o <<= 1) {
        int n = __shfl_up_sync(0xffffffffu, inc, o);
        if (lane >= o) inc += n;
    }
    if (lane == 31) wtot[warp] = inc;
    __syncthreads();
    if (t == 0) {
        int run = 0;
#pragma unroll
        for (int w = 0; w < 8; w++) { wpre[w] = run; run += wtot[w]; }
        mg_tiletot[mp * NT + tile] = run;
    }
    __syncthreads();

    int excl = wpre[warp] + inc - mysum;
#pragma unroll
    for (int k = 0; k < 8; k++) {
        int i = base + k;
        if (i < NN) off[i] = excl;
        excl += v[k];
    }
}

// Phase C (scanB folded in): each block sums tile totals below its tile.
__global__ __launch_bounds__(256) void mz_scanC() {
    int mp = blockIdx.y;
    int tile = blockIdx.x;
    int t = threadIdx.x;
    int toff = 0;
    for (int j = 0; j < NT; j++) {
        int tt = mg_tiletot[mp * NT + j];
        if (j < tile) toff += tt;
    }
    int* off = mg_off + (size_t)mp * NN;
    int* ctr = mg_ctr + (size_t)mp * NN;
    int base = tile * TILE + t * 8;
#pragma unroll
    for (int k = 0; k < 8; k++) {
        int i = base + k;
        if (i < NN) {
            int v = off[i] + toff;
            off[i] = v;
            ctr[i] = v;
        }
    }
}

// ---------------------------------------------------------------------------
// GEMM via mma.sync.m16n8k8 tf32. x tile in smem (pad 68); B frags via LDG
// from L1-resident tf32 W scratch (no W smem stage -> 3 blocks/SM).
// ---------------------------------------------------------------------------
#define XPAD 68
#define SX_FLOATS (128 * XPAD)
#define GEMM_SMEM (SX_FLOATS * 4)

__global__ __launch_bounds__(256) void mz_gemm_mma(const float* __restrict__ x) {
    extern __shared__ float smem[];
    float* sx = smem;
    int t = threadIdx.x;
    int wid = t >> 5;
    int lane = t & 31;
    int rowbase = blockIdx.x * 128;

    const float4* x4 = (const float4*)x;
    for (int i = t; i < 2048; i += 256) {
        int row = i >> 4;
        int q = i & 15;
        float4 v = make_float4(0.f, 0.f, 0.f, 0.f);
        int grow = rowbase + row;
        if (grow < NN) v = x4[(size_t)grow * 16 + q];
        uint4 u = make_uint4(f2tf32(v.x), f2tf32(v.y), f2tf32(v.z), f2tf32(v.w));
        *(uint4*)(sx + row * XPAD + q * 4) = u;
    }
    __syncthreads();

    int r = lane >> 2;
    int c = lane & 3;
    const uint32_t* sxu = (const uint32_t*)sx;

    uint32_t a[8][4];
    int ar0 = (wid * 16 + r) * XPAD;
    int ar1 = (wid * 16 + r + 8) * XPAD;
#pragma unroll
    for (int kk = 0; kk < 8; kk++) {
        int kc = kk * 8 + c;
        a[kk][0] = sxu[ar0 + kc];
        a[kk][1] = sxu[ar1 + kc];
        a[kk][2] = sxu[ar0 + kc + 4];
        a[kk][3] = sxu[ar1 + kc + 4];
    }

    int row0 = rowbase + wid * 16 + r;
#pragma unroll
    for (int mp = 0; mp < MP; mp++) {
        const uint32_t* wp = mg_wtf + mp * D * D;   // [k][n]
        float d[8][4];
#pragma unroll
        for (int nt = 0; nt < 8; nt++) {
            d[nt][0] = 0.f; d[nt][1] = 0.f; d[nt][2] = 0.f; d[nt][3] = 0.f;
        }
#pragma unroll
        for (int kk = 0; kk < 8; kk++) {
            int kb = (kk * 8 + c) * D + r;
#pragma unroll
            for (int nt = 0; nt < 8; nt++) {
                uint32_t b0 = wp[kb + nt * 8];
                uint32_t b1 = wp[kb + 4 * D + nt * 8];
                asm volatile(
                    "mma.sync.aligned.m16n8k8.row.col.f32.tf32.tf32.f32 "
                    "{%0,%1,%2,%3}, {%4,%5,%6,%7}, {%8,%9}, {%0,%1,%2,%3};"
                    : "+f"(d[nt][0]), "+f"(d[nt][1]), "+f"(d[nt][2]), "+f"(d[nt][3])
                    : "r"(a[kk][0]), "r"(a[kk][1]), "r"(a[kk][2]), "r"(a[kk][3]),
                      "r"(b0), "r"(b1));
            }
        }
        float* hout = mg_h + (size_t)mp * NN * D;
        if (row0 < NN) {
            float2* dst = (float2*)(hout + (size_t)row0 * D);
#pragma unroll
            for (int nt = 0; nt < 8; nt++)
                dst[nt * 4 + c] = make_float2(d[nt][0], d[nt][1]);
        }
        if (row0 + 8 < NN) {
            float2* dst = (float2*)(hout + (size_t)(row0 + 8) * D);
#pragma unroll
            for (int nt = 0; nt < 8; nt++)
                dst[nt * 4 + c] = make_float2(d[nt][2], d[nt][3]);
        }
    }
}

// ---------------------------------------------------------------------------
// Bin edges: packed (row, norm), norm precomputed.
// ---------------------------------------------------------------------------
__global__ void mz_fill(const int* __restrict__ ei32,
                        const float* __restrict__ ew) {
    int mp = blockIdx.y;
    int sh = mg_sh;
    size_t rowbase = (size_t)mp * 2 * NE;
    size_t colbase = rowbase + NE;
    const float* ewp = ew + (size_t)mp * NE;
    const float* dinv = mg_deg + (size_t)mp * NN;
    int* ctr = mg_ctr + (size_t)mp * NN;
    int2* edges = mg_edge + (size_t)mp * NE;
    int stride = gridDim.x * blockDim.x;
    for (int e = blockIdx.x * blockDim.x + threadIdx.x; e < NE; e += stride) {
        int r = ld_idx(ei32, rowbase + e, sh);
        int c = ld_idx(ei32, colbase + e, sh);
        float nm = dinv[r] * ewp[e] * dinv[c];
        int pos = atomicAdd(ctr + c, 1);
        edges[pos] = make_int2(r, __float_as_int(nm));
    }
}

// ---------------------------------------------------------------------------
// Gather: warp per dest node; 4-wide unroll; fused ReLU.
// ---------------------------------------------------------------------------
__global__ __launch_bounds__(256) void mz_gather(float* __restrict__ out,
                                                 int mp) {
    int node = blockIdx.x * 8 + (threadIdx.x >> 5);
    if (node >= NN) return;
    int lane = threadIdx.x & 31;
    const float* h = mg_h + (size_t)mp * NN * D;
    int start = mg_off[(size_t)mp * NN + node];
    int n = mg_count[(size_t)mp * NN + node];
    const int2* edges = mg_edge + (size_t)mp * NE + start;

    float2 acc = make_float2(0.f, 0.f);
    int j = 0;
    for (; j + 4 <= n; j += 4) {
        int2 e0 = edges[j], e1 = edges[j + 1], e2 = edges[j + 2], e3 = edges[j + 3];
        float2 v0 = *(const float2*)(h + (size_t)e0.x * D + lane * 2);
        float2 v1 = *(const float2*)(h + (size_t)e1.x * D + lane * 2);
        float2 v2 = *(const float2*)(h + (size_t)e2.x * D + lane * 2);
        float2 v3 = *(const float2*)(h + (size_t)e3.x * D + lane * 2);
        float n0 = __int_as_float(e0.y), n1 = __int_as_float(e1.y);
        float n2 = __int_as_float(e2.y), n3 = __int_as_float(e3.y);
        acc.x = fmaf(v0.x, n0, acc.x); acc.y = fmaf(v0.y, n0, acc.y);
        acc.x = fmaf(v1.x, n1, acc.x); acc.y = fmaf(v1.y, n1, acc.y);
        acc.x = fmaf(v2.x, n2, acc.x); acc.y = fmaf(v2.y, n2, acc.y);
        acc.x = fmaf(v3.x, n3, acc.x); acc.y = fmaf(v3.y, n3, acc.y);
    }
    for (; j < n; j++) {
        int2 e = edges[j];
        float nm = __int_as_float(e.y);
        float2 v = *(const float2*)(h + (size_t)e.x * D + lane * 2);
        acc.x = fmaf(v.x, nm, acc.x);
        acc.y = fmaf(v.y, nm, acc.y);
    }
    float2 o;
    o.x = fmaxf(acc.x, 0.f);
    o.y = fmaxf(acc.y, 0.f);
    *(float2*)(out + (size_t)mp * NN * D + (size_t)node * D + lane * 2) = o;
}

// ---------------------------------------------------------------------------
extern "C" void kernel_launch(void* const* d_in, const int* in_sizes, int n_in,
                              void* d_out, int out_size) {
    const float* x = (const float*)d_in[0];
    const float* W = (const float*)d_in[1];
    const int* ei32 = (const int*)d_in[2];
    const float* ew = (const float*)d_in[3];
    float* out = (float*)d_out;

    cudaFuncSetAttribute(mz_gemm_mma, cudaFuncAttributeMaxDynamicSharedMemorySize,
                         GEMM_SMEM);

    mz_init<<<(MP * NN + 255) / 256, 256>>>(ei32);            // #1
    mz_wcvt<<<(MP * D * D + 255) / 256, 256>>>(W);            // #2
    mz_hist<<<dim3(512, MP), 256>>>(ei32, ew);                // #3
    mz_gemm_mma<<<(NN + 127) / 128, 256, GEMM_SMEM>>>(x);     // #4 (profiled)
    mz_scanA<<<dim3(NT, MP), 256>>>();                        // #5
    mz_scanC<<<dim3(NT, MP), 256>>>();                        // #6
    mz_fill<<<dim3(512, MP), 256>>>(ei32, ew);                // #7
    for (int mp = 0; mp < MP; mp++) {                         // #8-10
        mz_gather<<<(NN + 7) / 8, 256>>>(out, mp);
    }
}

// round 11
// speedup vs baseline: 1.1034x; 1.1034x over previous
#include <cuda_runtime.h>
#include <cstdint>

#define NN 100000
#define NE 1000000
#define D  64
#define MP 3

#define TILE 2048
#define NT ((NN + TILE - 1) / TILE)

// Scratch (__device__ globals per allocation-free rule)
__device__ float mg_h[(size_t)MP * NN * D];       // transformed features
__device__ float mg_deg[MP * NN];                 // dinv
__device__ unsigned long long mg_pack[MP * NN];   // count<<44 | fixp deg sum
__device__ int   mg_count[MP * NN];               // edges per dest node
__device__ int   mg_off[MP * NN];                 // CSR start offsets
__device__ int   mg_ctr[MP * NN];                 // running fill cursors
__device__ int2  mg_edge[(size_t)MP * NE];        // packed (src row, norm)
__device__ int   mg_tiletot[MP * NT];
__device__ int   mg_sh;                           // 0 = int32 idx, 1 = int64

// ---------------------------------------------------------------------------
// Fused: zero pack; block 0 warp 0 sniffs edge dtype.
// ---------------------------------------------------------------------------
__global__ void mz_init(const int* __restrict__ ei32) {
    int i = blockIdx.x * blockDim.x + threadIdx.x;
    if (i < MP * NN) mg_pack[i] = 0ull;
    if (blockIdx.x == 0 && threadIdx.x < 32) {
        int t = threadIdx.x;
        int nz = 0;
        for (int k = 0; k < 8; k++) {
            int s = (t * 8 + k) * 1009;
            nz |= (ei32[2 * s + 1] != 0);
        }
        unsigned b = __ballot_sync(0xffffffffu, nz);
        if (t == 0) mg_sh = (b == 0u) ? 1 : 0;
    }
}

__device__ __forceinline__ int ld_idx(const int* p, size_t pos, int sh) {
    return p[pos << sh];
}

// ---------------------------------------------------------------------------
// Single packed u64 atomic per edge: count++ AND deg += ew (2^-24 fixpoint)
// ---------------------------------------------------------------------------
__global__ void mz_hist(const int* __restrict__ ei32,
                        const float* __restrict__ ew) {
    int mp = blockIdx.y;
    int sh = mg_sh;
    size_t colbase = (size_t)mp * 2 * NE + NE;
    const float* ewp = ew + (size_t)mp * NE;
    unsigned long long* pk = mg_pack + (size_t)mp * NN;
    int stride = gridDim.x * blockDim.x;
    for (int e = blockIdx.x * blockDim.x + threadIdx.x; e < NE; e += stride) {
        int c = ld_idx(ei32, colbase + e, sh);
        unsigned long long frac =
            (unsigned long long)__float2uint_rn(ewp[e] * 16777216.0f);
        atomicAdd(pk + c, (1ull << 44) | frac);
    }
}

// ---------------------------------------------------------------------------
// Phase A of decoupled scan, fused with pack -> (count, dinv).
// ---------------------------------------------------------------------------
__global__ __launch_bounds__(256) void mz_scanA() {
    __shared__ int wtot[8];
    __shared__ int wpre[8];
    int mp = blockIdx.y;
    int tile = blockIdx.x;
    int t = threadIdx.x;
    int lane = t & 31;
    int warp = t >> 5;
    const unsigned long long* pk = mg_pack + (size_t)mp * NN;
    int* cnt = mg_count + (size_t)mp * NN;
    int* off = mg_off + (size_t)mp * NN;
    float* deg = mg_deg + (size_t)mp * NN;

    int base = tile * TILE + t * 8;
    int v[8];
#pragma unroll
    for (int k = 0; k < 8; k++) {
        int i = base + k;
        if (i < NN) {
            unsigned long long p = pk[i];
            int c = (int)(p >> 44);
            float d = (float)(p & ((1ull << 44) - 1)) * (1.0f / 16777216.0f);
            v[k] = c;
            cnt[i] = c;
            deg[i] = (d > 0.f) ? rsqrtf(d) : 0.f;
        } else {
            v[k] = 0;
        }
    }
    int mysum = 0;
#pragma unroll
    for (int k = 0; k < 8; k++) mysum += v[k];

    int inc = mysum;
#pragma unroll
    for (int o = 1; o < 32; o <<= 1) {
        int n = __shfl_up_sync(0xffffffffu, inc, o);
        if (lane >= o) inc += n;
    }
    if (lane == 31) wtot[warp] = inc;
    __syncthreads();
    if (t == 0) {
        int run = 0;
#pragma unroll
        for (int w = 0; w < 8; w++) { wpre[w] = run; run += wtot[w]; }
        mg_tiletot[mp * NT + tile] = run;
    }
    __syncthreads();

    int excl = wpre[warp] + inc - mysum;
#pragma unroll
    for (int k = 0; k < 8; k++) {
        int i = base + k;
        if (i < NN) off[i] = excl;
        excl += v[k];
    }
}

// Phase C (scanB folded in): each block sums tile totals below its tile.
__global__ __launch_bounds__(256) void mz_scanC() {
    int mp = blockIdx.y;
    int tile = blockIdx.x;
    int t = threadIdx.x;
    int toff = 0;
    for (int j = 0; j < NT; j++) {
        int tt = mg_tiletot[mp * NT + j];
        if (j < tile) toff += tt;
    }
    int* off = mg_off + (size_t)mp * NN;
    int* ctr = mg_ctr + (size_t)mp * NN;
    int base = tile * TILE + t * 8;
#pragma unroll
    for (int k = 0; k < 8; k++) {
        int i = base + k;
        if (i < NN) {
            int v = off[i] + toff;
            off[i] = v;
            ctr[i] = v;
        }
    }
}

// ---------------------------------------------------------------------------
// GEMM via mma.sync.m16n8k8 tf32 (R9 configuration: W staged in smem).
// Block: 256 thr = 8 warps x 16 rows = 128-row tile; all 3 mp per block.
// smem: x tile padded to 68 floats/row; W padded to 72 floats/row
// (both paddings make the fragment LDS patterns bank-conflict-free).
// ---------------------------------------------------------------------------
#define XPAD 68
#define WPAD 72
#define SX_FLOATS (128 * XPAD)
#define SW_FLOATS (MP * 64 * WPAD)
#define GEMM_SMEM ((SX_FLOATS + SW_FLOATS) * 4)

__device__ __forceinline__ uint32_t f2tf32(float f) {
    uint32_t u;
    asm("cvt.rna.tf32.f32 %0, %1;" : "=r"(u) : "f"(f));
    return u;
}

__global__ __launch_bounds__(256) void mz_gemm_mma(const float* __restrict__ x,
                                                   const float* __restrict__ W) {
    extern __shared__ float smem[];
    float* sx = smem;                 // [128][XPAD]
    float* sW = smem + SX_FLOATS;     // [MP][64][WPAD]
    int t = threadIdx.x;
    int wid = t >> 5;
    int lane = t & 31;
    int rowbase = blockIdx.x * 128;

    // Stage x tile (tf32-rounded)
    const float4* x4 = (const float4*)x;
    for (int i = t; i < 2048; i += 256) {
        int row = i >> 4;
        int q = i & 15;
        float4 v = make_float4(0.f, 0.f, 0.f, 0.f);
        int grow = rowbase + row;
        if (grow < NN) v = x4[(size_t)grow * 16 + q];
        uint4 u = make_uint4(f2tf32(v.x), f2tf32(v.y), f2tf32(v.z), f2tf32(v.w));
        *(uint4*)(sx + row * XPAD + q * 4) = u;
    }
    // Stage all 3 W (tf32-rounded)
    const float4* W4 = (const float4*)W;
    for (int i = t; i < MP * 64 * 16; i += 256) {
        int mp = i >> 10;
        int rem = i & 1023;
        int k = rem >> 4;
        int q = rem & 15;
        float4 v = W4[i];
        uint4 u = make_uint4(f2tf32(v.x), f2tf32(v.y), f2tf32(v.z), f2tf32(v.w));
        *(uint4*)(sW + mp * 64 * WPAD + k * WPAD + q * 4) = u;
    }
    __syncthreads();

    int r = lane >> 2;                // 0..7
    int c = lane & 3;                 // 0..3
    const uint32_t* sxu = (const uint32_t*)sx;
    const uint32_t* sWu = (const uint32_t*)sW;

    // A fragments for this warp's 16 rows, all 8 k-steps (32 regs)
    uint32_t a[8][4];
    int ar0 = (wid * 16 + r) * XPAD;
    int ar1 = (wid * 16 + r + 8) * XPAD;
#pragma unroll
    for (int kk = 0; kk < 8; kk++) {
        int kc = kk * 8 + c;
        a[kk][0] = sxu[ar0 + kc];
        a[kk][1] = sxu[ar1 + kc];
        a[kk][2] = sxu[ar0 + kc + 4];
        a[kk][3] = sxu[ar1 + kc + 4];
    }

    int row0 = rowbase + wid * 16 + r;
#pragma unroll
    for (int mp = 0; mp < MP; mp++) {
        const uint32_t* wp = sWu + mp * 64 * WPAD;
        float d[8][4];
#pragma unroll
        for (int nt = 0; nt < 8; nt++) {
            d[nt][0] = 0.f; d[nt][1] = 0.f; d[nt][2] = 0.f; d[nt][3] = 0.f;
        }
#pragma unroll
        for (int kk = 0; kk < 8; kk++) {
            int kb = (kk * 8 + c) * WPAD + r;   // B frag: k = kk*8+c, n = nt*8+r
#pragma unroll
            for (int nt = 0; nt < 8; nt++) {
                uint32_t b0 = wp[kb + nt * 8];
                uint32_t b1 = wp[kb + 4 * WPAD + nt * 8];
                asm volatile(
                    "mma.sync.aligned.m16n8k8.row.col.f32.tf32.tf32.f32 "
                    "{%0,%1,%2,%3}, {%4,%5,%6,%7}, {%8,%9}, {%0,%1,%2,%3};"
                    : "+f"(d[nt][0]), "+f"(d[nt][1]), "+f"(d[nt][2]), "+f"(d[nt][3])
                    : "r"(a[kk][0]), "r"(a[kk][1]), "r"(a[kk][2]), "r"(a[kk][3]),
                      "r"(b0), "r"(b1));
            }
        }
        float* hout = mg_h + (size_t)mp * NN * D;
        if (row0 < NN) {
            float2* dst = (float2*)(hout + (size_t)row0 * D);
#pragma unroll
            for (int nt = 0; nt < 8; nt++)
                dst[nt * 4 + c] = make_float2(d[nt][0], d[nt][1]);
        }
        if (row0 + 8 < NN) {
            float2* dst = (float2*)(hout + (size_t)(row0 + 8) * D);
#pragma unroll
            for (int nt = 0; nt < 8; nt++)
                dst[nt * 4 + c] = make_float2(d[nt][2], d[nt][3]);
        }
    }
}

// ---------------------------------------------------------------------------
// Bin edges: packed (row, norm), norm precomputed.
// ---------------------------------------------------------------------------
__global__ void mz_fill(const int* __restrict__ ei32,
                        const float* __restrict__ ew) {
    int mp = blockIdx.y;
    int sh = mg_sh;
    size_t rowbase = (size_t)mp * 2 * NE;
    size_t colbase = rowbase + NE;
    const float* ewp = ew + (size_t)mp * NE;
    const float* dinv = mg_deg + (size_t)mp * NN;
    int* ctr = mg_ctr + (size_t)mp * NN;
    int2* edges = mg_edge + (size_t)mp * NE;
    int stride = gridDim.x * blockDim.x;
    for (int e = blockIdx.x * blockDim.x + threadIdx.x; e < NE; e += stride) {
        int r = ld_idx(ei32, rowbase + e, sh);
        int c = ld_idx(ei32, colbase + e, sh);
        float nm = dinv[r] * ewp[e] * dinv[c];
        int pos = atomicAdd(ctr + c, 1);
        edges[pos] = make_int2(r, __float_as_int(nm));
    }
}

// ---------------------------------------------------------------------------
// Gather: warp per dest node; 4-wide unroll; fused ReLU.
// ---------------------------------------------------------------------------
__global__ __launch_bounds__(256) void mz_gather(float* __restrict__ out,
                                                 int mp) {
    int node = blockIdx.x * 8 + (threadIdx.x >> 5);
    if (node >= NN) return;
    int lane = threadIdx.x & 31;
    const float* h = mg_h + (size_t)mp * NN * D;
    int start = mg_off[(size_t)mp * NN + node];
    int n = mg_count[(size_t)mp * NN + node];
    const int2* edges = mg_edge + (size_t)mp * NE + start;

    float2 acc = make_float2(0.f, 0.f);
    int j = 0;
    for (; j + 4 <= n; j += 4) {
        int2 e0 = edges[j], e1 = edges[j + 1], e2 = edges[j + 2], e3 = edges[j + 3];
        float2 v0 = *(const float2*)(h + (size_t)e0.x * D + lane * 2);
        float2 v1 = *(const float2*)(h + (size_t)e1.x * D + lane * 2);
        float2 v2 = *(const float2*)(h + (size_t)e2.x * D + lane * 2);
        float2 v3 = *(const float2*)(h + (size_t)e3.x * D + lane * 2);
        float n0 = __int_as_float(e0.y), n1 = __int_as_float(e1.y);
        float n2 = __int_as_float(e2.y), n3 = __int_as_float(e3.y);
        acc.x = fmaf(v0.x, n0, acc.x); acc.y = fmaf(v0.y, n0, acc.y);
        acc.x = fmaf(v1.x, n1, acc.x); acc.y = fmaf(v1.y, n1, acc.y);
        acc.x = fmaf(v2.x, n2, acc.x); acc.y = fmaf(v2.y, n2, acc.y);
        acc.x = fmaf(v3.x, n3, acc.x); acc.y = fmaf(v3.y, n3, acc.y);
    }
    for (; j < n; j++) {
        int2 e = edges[j];
        float nm = __int_as_float(e.y);
        float2 v = *(const float2*)(h + (size_t)e.x * D + lane * 2);
        acc.x = fmaf(v.x, nm, acc.x);
        acc.y = fmaf(v.y, nm, acc.y);
    }
    float2 o;
    o.x = fmaxf(acc.x, 0.f);
    o.y = fmaxf(acc.y, 0.f);
    *(float2*)(out + (size_t)mp * NN * D + (size_t)node * D + lane * 2) = o;
}

// ---------------------------------------------------------------------------
extern "C" void kernel_launch(void* const* d_in, const int* in_sizes, int n_in,
                              void* d_out, int out_size) {
    const float* x = (const float*)d_in[0];
    const float* W = (const float*)d_in[1];
    const int* ei32 = (const int*)d_in[2];
    const float* ew = (const float*)d_in[3];
    float* out = (float*)d_out;

    cudaFuncSetAttribute(mz_gemm_mma, cudaFuncAttributeMaxDynamicSharedMemorySize,
                         GEMM_SMEM);

    mz_init<<<(MP * NN + 255) / 256, 256>>>(ei32);            // #1
    mz_hist<<<dim3(512, MP), 256>>>(ei32, ew);                // #2
    mz_scanA<<<dim3(NT, MP), 256>>>();                        // #3
    mz_gemm_mma<<<(NN + 127) / 128, 256, GEMM_SMEM>>>(x, W);  // #4 (profiled)
    mz_scanC<<<dim3(NT, MP), 256>>>();                        // #5
    mz_fill<<<dim3(512, MP), 256>>>(ei32, ew);                // #6
    for (int mp = 0; mp < MP; mp++) {                         // #7-9
        mz_gather<<<(NN + 7) / 8, 256>>>(out, mp);
    }
}